// round 7
// baseline (speedup 1.0000x reference)
#include <cuda_runtime.h>
#include <cstdint>

// Problem constants (B=256, T=2048, D=128)
#define BB 256
#define TT 2048
#define DD 128
#define MM (BB * TT)          // 524288 rows of the projection GEMM

// Scratch: [m][3][128] fp32 : j=0 -> E = X@We^T + be
//                             j=1 -> L = sigmoid(X@Wl^T + bl)
//                             j=2 -> W = sigmoid(X@Ww^T + bw)
__device__ float g_elw[(size_t)MM * 384];

// ---------------------------------------------------------------------------
// helpers
// ---------------------------------------------------------------------------
__device__ __forceinline__ uint32_t f2tf(float f) {
    uint32_t r;
    asm("cvt.rna.tf32.f32 %0, %1;" : "=r"(r) : "f"(f));
    return r;
}

__device__ __forceinline__ unsigned long long ffma2(unsigned long long a,
                                                    unsigned long long b,
                                                    unsigned long long c) {
    unsigned long long d;
    asm("fma.rn.f32x2 %0, %1, %2, %3;" : "=l"(d) : "l"(a), "l"(b), "l"(c));
    return d;
}

__device__ __forceinline__ float2 u2f2(unsigned long long v) {
    float2 r;
    asm("mov.b64 {%0,%1}, %2;" : "=f"(r.x), "=f"(r.y) : "l"(v));
    return r;
}

__device__ __forceinline__ void cp_async16(uint32_t dst_smem, const void* src) {
    asm volatile("cp.async.cg.shared.global [%0], [%1], 16;\n"
                 :: "r"(dst_smem), "l"(src));
}

__device__ __forceinline__ float tanh_approx(float x) {
    float y;
    asm("tanh.approx.f32 %0, %1;" : "=f"(y) : "f"(x));
    return y;
}

// ---------------------------------------------------------------------------
// Kernel 1: fused 3-way projection GEMM (tf32 mma.sync), epilogue bias+sigmoid
// CTA: 256 threads (8 warps), M_TILE=128, N=128 per weight, K=128 in 2 halves.
// 6 pipeline stages (j,kc); W staged via register prefetch + double-buffered
// Ws in smem -> one __syncthreads per stage.
// smem: Xs[128][132] tf32 (67.6KB) + Ws[2][128][68] tf32 (69.6KB) = 137.2KB.
// ---------------------------------------------------------------------------
__global__ __launch_bounds__(256) void proj_kernel(
    const float* __restrict__ X,
    const float* __restrict__ We, const float* __restrict__ be,
    const float* __restrict__ Wl, const float* __restrict__ bl,
    const float* __restrict__ Ww, const float* __restrict__ bw)
{
    extern __shared__ uint32_t smem[];
    uint32_t* Xs = smem;                  // [128][132] tf32
    uint32_t* Wsb = smem + 128 * 132;     // [2][128][68] tf32

    const int tid  = threadIdx.x;
    const int warp = tid >> 5;
    const int lane = tid & 31;
    const int g    = lane >> 2;           // 0..7
    const int c    = lane & 3;            // 0..3
    const long m0  = (long)blockIdx.x * 128;
    const int r0   = warp * 16 + g;

    // ---- load X tile (coalesced float4), convert to tf32 into smem ----
    const float4* X4 = (const float4*)(X + m0 * DD);
    #pragma unroll
    for (int i = 0; i < 16; i++) {
        int idx = tid + i * 256;          // 0..4095 float4s
        int row = idx >> 5;               // 32 float4 per row
        int c4  = idx & 31;
        float4 v = X4[row * 32 + c4];
        uint4 u = make_uint4(f2tf(v.x), f2tf(v.y), f2tf(v.z), f2tf(v.w));
        *(uint4*)&Xs[row * 132 + c4 * 4] = u;
    }

    // ---- stage-0 weight prefetch (We, k-half 0) into registers ----
    float4 wreg[8];
    {
        #pragma unroll
        for (int i = 0; i < 8; i++) {
            int idx = tid + i * 256;      // 0..2047 float4s
            int row = idx >> 4;
            int c4  = idx & 15;
            wreg[i] = *(const float4*)&We[row * 128 + c4 * 4];
        }
    }
    __syncthreads();   // Xs ready

    float acc[16][4];

    #pragma unroll 1
    for (int s = 0; s < 6; s++) {
        const int j  = s >> 1;
        const int kc = s & 1;
        uint32_t* Ws = Wsb + (s & 1) * (128 * 68);

        if (kc == 0) {
            #pragma unroll
            for (int nt = 0; nt < 16; nt++)
                #pragma unroll
                for (int q = 0; q < 4; q++) acc[nt][q] = 0.0f;
        }

        // ---- STS current stage weights (with tf32 convert) ----
        #pragma unroll
        for (int i = 0; i < 8; i++) {
            int idx = tid + i * 256;
            int row = idx >> 4;
            int c4  = idx & 15;
            float4 v = wreg[i];
            uint4 u = make_uint4(f2tf(v.x), f2tf(v.y), f2tf(v.z), f2tf(v.w));
            *(uint4*)&Ws[row * 68 + c4 * 4] = u;
        }

        // ---- register-prefetch next stage's weights ----
        if (s < 5) {
            const int s2  = s + 1;
            const int j2  = s2 >> 1;
            const int kc2 = s2 & 1;
            const float* Wn = (j2 == 0) ? We : ((j2 == 1) ? Wl : Ww);
            #pragma unroll
            for (int i = 0; i < 8; i++) {
                int idx = tid + i * 256;
                int row = idx >> 4;
                int c4  = idx & 15;
                wreg[i] = *(const float4*)&Wn[row * 128 + kc2 * 64 + c4 * 4];
            }
        }
        __syncthreads();   // Ws for this stage visible; other buffer free

        // ---- mma loop (a-frags re-read from resident Xs) ----
        #pragma unroll
        for (int kt = 0; kt < 8; kt++) {
            const int k0 = (kc * 8 + kt) * 8 + c;
            uint32_t a0 = Xs[r0 * 132 + k0];
            uint32_t a1 = Xs[(r0 + 8) * 132 + k0];
            uint32_t a2 = Xs[r0 * 132 + k0 + 4];
            uint32_t a3 = Xs[(r0 + 8) * 132 + k0 + 4];
            #pragma unroll
            for (int nt = 0; nt < 16; nt++) {
                int n  = nt * 8 + g;
                int kk = kt * 8 + c;
                uint32_t b0 = Ws[n * 68 + kk];
                uint32_t b1 = Ws[n * 68 + kk + 4];
                asm volatile(
                    "mma.sync.aligned.m16n8k8.row.col.f32.tf32.tf32.f32 "
                    "{%0,%1,%2,%3}, {%4,%5,%6,%7}, {%8,%9}, {%0,%1,%2,%3};\n"
                    : "+f"(acc[nt][0]), "+f"(acc[nt][1]),
                      "+f"(acc[nt][2]), "+f"(acc[nt][3])
                    : "r"(a0), "r"(a1), "r"(a2), "r"(a3),
                      "r"(b0), "r"(b1));
            }
        }

        // ---- epilogue after second k-half: bias (+sigmoid), store ----
        if (kc == 1) {
            const float* bj = (j == 0) ? be : ((j == 1) ? bl : bw);
            long row0 = m0 + warp * 16 + g;
            #pragma unroll
            for (int nt = 0; nt < 16; nt++) {
                int col = nt * 8 + 2 * c;
                float2 bb = *(const float2*)&bj[col];
                float v0 = acc[nt][0] + bb.x;
                float v1 = acc[nt][1] + bb.y;
                float v2 = acc[nt][2] + bb.x;
                float v3 = acc[nt][3] + bb.y;
                if (j > 0) {
                    v0 = 1.0f / (1.0f + __expf(-v0));
                    v1 = 1.0f / (1.0f + __expf(-v1));
                    v2 = 1.0f / (1.0f + __expf(-v2));
                    v3 = 1.0f / (1.0f + __expf(-v3));
                }
                *(float2*)&g_elw[(row0 * 3 + j) * 128 + col]       = make_float2(v0, v1);
                *(float2*)&g_elw[((row0 + 8) * 3 + j) * 128 + col] = make_float2(v2, v3);
            }
        }
    }
}

// ---------------------------------------------------------------------------
// Kernel 2: persistent recurrence. 128 CTAs x 256 threads; CTA owns 2 batch
// rows DECOUPLED via named barriers (one bar.sync per row per step).
// Belief double-buffered in smem (no second barrier). 4x16-deep FFMA2 chains.
// e/l/w streamed via depth-4 cp.async ring; tanh.approx epilogue.
// ---------------------------------------------------------------------------
__global__ __launch_bounds__(256, 1) void recur_kernel(
    const float* __restrict__ Wp, const float* __restrict__ bp,
    float* __restrict__ out)
{
    __shared__ __align__(16) float bel[2][2][128];    // [buf][row][lane]
    __shared__ __align__(16) float ring[4][2][384];   // [slot][row][E|L|W]

    const int tid   = threadIdx.x;
    const int r     = tid >> 7;      // 0..1 local batch row (warp-aligned)
    const int e     = tid & 127;     // output lane
    const int rlane = tid & 127;
    const long b    = (long)blockIdx.x * 2 + r;
    const int barid = 1 + r;

    // Wp row e as packed f32x2 (128 registers)
    unsigned long long wp[64];
    const unsigned long long* wrow = (const unsigned long long*)(Wp + e * 128);
    #pragma unroll
    for (int i = 0; i < 64; i++) wp[i] = wrow[i];
    const float bias = bp[e];

    bel[0][r][e] = 0.0f;
    float belr = 0.0f;

    // prefetch lane assignment: first 96 threads of each row move that row's
    // 1536B (E|L|W) per step, 16B per thread.
    const bool cp_on = (rlane < 96);
    const int  cp_k  = rlane * 4;
    const float* src_base = g_elw + ((long)b * TT) * 384 + cp_k;
    const uint32_t ring_base =
        (uint32_t)__cvta_generic_to_shared(&ring[0][0][0]);
    const uint32_t dst_off = (uint32_t)((r * 384 + cp_k) * 4);

    // prologue: fill slots 0..2 (t = 0..2), one commit group per slot
    for (int sl = 0; sl < 3; sl++) {
        if (cp_on) cp_async16(ring_base + (uint32_t)sl * 3072u + dst_off,
                              src_base + (long)sl * 384);
        asm volatile("cp.async.commit_group;\n");
    }

    float* outp = out + b * (long)TT * 128 + e;

    for (int t = 0; t < TT; t++) {
        const int slot = t & 3;
        const int cur  = t & 1;

        // group committed for step t completes (<=2 younger remain in flight)
        asm volatile("cp.async.wait_group 2;\n");
        // one barrier: ring[slot] + prev step's belief STS visible row-wide;
        // also licenses overwrite of slot (t+3)&3 == (t-1)&3
        asm volatile("bar.sync %0, %1;\n" :: "r"(barid), "r"(128) : "memory");

        // refill slot (t+3)&3 with step t+3
        if (t + 3 < TT && cp_on)
            cp_async16(ring_base + (uint32_t)((t + 3) & 3) * 3072u + dst_off,
                       src_base + (long)(t + 3) * 384);
        asm volatile("cp.async.commit_group;\n");

        float ev = ring[slot][r][e];
        float lv = ring[slot][r][128 + e];
        float wv = ring[slot][r][256 + e];

        const ulonglong2* bl2 = (const ulonglong2*)&bel[cur][r][0];
        unsigned long long acc0 = 0ull, acc1 = 0ull, acc2 = 0ull, acc3 = 0ull;
        #pragma unroll
        for (int i = 0; i < 16; i++) {
            ulonglong2 b0 = bl2[2 * i];
            ulonglong2 b1 = bl2[2 * i + 1];
            acc0 = ffma2(wp[4 * i],     b0.x, acc0);
            acc1 = ffma2(wp[4 * i + 1], b0.y, acc1);
            acc2 = ffma2(wp[4 * i + 2], b1.x, acc2);
            acc3 = ffma2(wp[4 * i + 3], b1.y, acc3);
        }
        float2 s0 = u2f2(acc0);
        float2 s1 = u2f2(acc1);
        float2 s2 = u2f2(acc2);
        float2 s3 = u2f2(acc3);
        float pre  = ((s0.x + s0.y) + (s1.x + s1.y)) +
                     ((s2.x + s2.y) + (s3.x + s3.y)) + bias + ev;
        float cand = tanh_approx(pre);
        float nb   = lv * belr + wv * cand;

        outp[(long)t * 128] = nb;
        belr = nb;
        bel[cur ^ 1][r][e] = nb;   // write to other buffer; no extra barrier
    }
}

// ---------------------------------------------------------------------------
// launch
// ---------------------------------------------------------------------------
extern "C" void kernel_launch(void* const* d_in, const int* in_sizes, int n_in,
                              void* d_out, int out_size) {
    const float* X  = (const float*)d_in[0];
    const float* We = (const float*)d_in[1];
    const float* be = (const float*)d_in[2];
    const float* Wp = (const float*)d_in[3];
    const float* bp = (const float*)d_in[4];
    const float* Wl = (const float*)d_in[5];
    const float* bl = (const float*)d_in[6];
    const float* Ww = (const float*)d_in[7];
    const float* bw = (const float*)d_in[8];
    float* out = (float*)d_out;

    // Xs (67.6KB) + double-buffered Ws (69.6KB) = 137.2KB dynamic smem.
    cudaFuncSetAttribute(proj_kernel,
                         cudaFuncAttributeMaxDynamicSharedMemorySize, 137216);

    proj_kernel<<<MM / 128, 256, 137216>>>(X, We, be, Wl, bl, Ww, bw);
    recur_kernel<<<BB / 2, 256>>>(Wp, bp, out);
}

// round 8
// speedup vs baseline: 1.0351x; 1.0351x over previous
#include <cuda_runtime.h>
#include <cstdint>

// Problem constants (B=256, T=2048, D=128)
#define BB 256
#define TT 2048
#define DD 128
#define MM (BB * TT)

// Scratch: [m][3][128] fp32 : j=0 -> E = X@We^T + be
//                             j=1 -> L = sigmoid(X@Wl^T + bl)
//                             j=2 -> W = sigmoid(X@Ww^T + bw)
__device__ float g_elw[(size_t)MM * 384];

// ---------------------------------------------------------------------------
// helpers
// ---------------------------------------------------------------------------
__device__ __forceinline__ uint32_t f2tf(float f) {
    uint32_t r;
    asm("cvt.rna.tf32.f32 %0, %1;" : "=r"(r) : "f"(f));
    return r;
}

__device__ __forceinline__ unsigned long long ffma2(unsigned long long a,
                                                    unsigned long long b,
                                                    unsigned long long c) {
    unsigned long long d;
    asm("fma.rn.f32x2 %0, %1, %2, %3;" : "=l"(d) : "l"(a), "l"(b), "l"(c));
    return d;
}

__device__ __forceinline__ float2 u2f2(unsigned long long v) {
    float2 r;
    asm("mov.b64 {%0,%1}, %2;" : "=f"(r.x), "=f"(r.y) : "l"(v));
    return r;
}

__device__ __forceinline__ void cp_async16(uint32_t dst_smem, const void* src) {
    asm volatile("cp.async.cg.shared.global [%0], [%1], 16;\n"
                 :: "r"(dst_smem), "l"(src));
}

__device__ __forceinline__ float tanh_approx(float x) {
    float y;
    asm("tanh.approx.f32 %0, %1;" : "=f"(y) : "f"(x));
    return y;
}

// ---------------------------------------------------------------------------
// Kernel 1: fused 3-way projection GEMM (tf32 mma.sync), bias+sigmoid epilogue
// M_TILE=64 so smem = Xs[64][132] (33.8KB) + Ws[128][68] (34.8KB) = 68.6KB
// -> 2 CTAs/SM; cross-CTA overlap hides per-stage staging barriers.
// 8 warps = 4 m-tiles (16 rows) x 2 n-halves (64 cols). 6 stages (3 W x 2 kc).
// ---------------------------------------------------------------------------
__global__ __launch_bounds__(256) void proj_kernel(
    const float* __restrict__ X,
    const float* __restrict__ We, const float* __restrict__ be,
    const float* __restrict__ Wl, const float* __restrict__ bl,
    const float* __restrict__ Ww, const float* __restrict__ bw)
{
    extern __shared__ uint32_t smem[];
    uint32_t* Xs = smem;                 // [64][132] tf32
    uint32_t* Ws = smem + 64 * 132;      // [128][68] tf32

    const int tid  = threadIdx.x;
    const int warp = tid >> 5;
    const int lane = tid & 31;
    const int g    = lane >> 2;          // 0..7
    const int c    = lane & 3;           // 0..3
    const int mt   = warp & 3;           // m-tile (16 rows)
    const int nh   = warp >> 2;          // n-half (64 cols)
    const long m0  = (long)blockIdx.x * 64;
    const int r0   = mt * 16 + g;

    // ---- load X tile (coalesced float4), convert to tf32 into smem ----
    const float4* X4 = (const float4*)(X + m0 * DD);
    #pragma unroll
    for (int i = 0; i < 8; i++) {
        int idx = tid + i * 256;         // 0..2047 float4s
        int row = idx >> 5;              // 32 float4 per row
        int c4  = idx & 31;
        float4 v = X4[row * 32 + c4];
        uint4 u = make_uint4(f2tf(v.x), f2tf(v.y), f2tf(v.z), f2tf(v.w));
        *(uint4*)&Xs[row * 132 + c4 * 4] = u;
    }

    float acc[8][4];

    #pragma unroll 1
    for (int s = 0; s < 6; s++) {
        const int j  = s >> 1;
        const int kc = s & 1;
        const float* Wj = (j == 0) ? We : ((j == 1) ? Wl : Ww);

        if (kc == 0) {
            #pragma unroll
            for (int nt = 0; nt < 8; nt++)
                #pragma unroll
                for (int q = 0; q < 4; q++) acc[nt][q] = 0.0f;
        }

        __syncthreads();   // previous stage's Ws consumers done (s=0: Xs ready)

        // stage W[:, kc*64 : kc*64+64) as tf32
        #pragma unroll
        for (int i = 0; i < 8; i++) {
            int idx = tid + i * 256;     // 0..2047 float4s
            int row = idx >> 4;          // 16 float4 per row-chunk
            int c4  = idx & 15;
            float4 v = *(const float4*)&Wj[row * 128 + kc * 64 + c4 * 4];
            uint4 u = make_uint4(f2tf(v.x), f2tf(v.y), f2tf(v.z), f2tf(v.w));
            *(uint4*)&Ws[row * 68 + c4 * 4] = u;
        }
        __syncthreads();

        // ---- mma loop ----
        #pragma unroll
        for (int kt = 0; kt < 8; kt++) {
            const int kx = kc * 64 + kt * 8 + c;   // Xs column
            uint32_t a0 = Xs[r0 * 132 + kx];
            uint32_t a1 = Xs[(r0 + 8) * 132 + kx];
            uint32_t a2 = Xs[r0 * 132 + kx + 4];
            uint32_t a3 = Xs[(r0 + 8) * 132 + kx + 4];
            #pragma unroll
            for (int nt = 0; nt < 8; nt++) {
                int n  = nh * 64 + nt * 8 + g;
                int kk = kt * 8 + c;
                uint32_t b0 = Ws[n * 68 + kk];
                uint32_t b1 = Ws[n * 68 + kk + 4];
                asm volatile(
                    "mma.sync.aligned.m16n8k8.row.col.f32.tf32.tf32.f32 "
                    "{%0,%1,%2,%3}, {%4,%5,%6,%7}, {%8,%9}, {%0,%1,%2,%3};\n"
                    : "+f"(acc[nt][0]), "+f"(acc[nt][1]),
                      "+f"(acc[nt][2]), "+f"(acc[nt][3])
                    : "r"(a0), "r"(a1), "r"(a2), "r"(a3),
                      "r"(b0), "r"(b1));
            }
        }

        // ---- epilogue after second k-half: bias (+sigmoid), store ----
        if (kc == 1) {
            const float* bj = (j == 0) ? be : ((j == 1) ? bl : bw);
            long row0 = m0 + mt * 16 + g;
            #pragma unroll
            for (int nt = 0; nt < 8; nt++) {
                int col = nh * 64 + nt * 8 + 2 * c;
                float2 bb = *(const float2*)&bj[col];
                float v0 = acc[nt][0] + bb.x;
                float v1 = acc[nt][1] + bb.y;
                float v2 = acc[nt][2] + bb.x;
                float v3 = acc[nt][3] + bb.y;
                if (j > 0) {
                    v0 = 1.0f / (1.0f + __expf(-v0));
                    v1 = 1.0f / (1.0f + __expf(-v1));
                    v2 = 1.0f / (1.0f + __expf(-v2));
                    v3 = 1.0f / (1.0f + __expf(-v3));
                }
                *(float2*)&g_elw[(row0 * 3 + j) * 128 + col]       = make_float2(v0, v1);
                *(float2*)&g_elw[((row0 + 8) * 3 + j) * 128 + col] = make_float2(v2, v3);
            }
        }
    }
}

// ---------------------------------------------------------------------------
// Kernel 2: persistent recurrence, half-K split for 4 streams/SMSP.
// 128 CTAs x 512 threads; CTA owns 2 batch rows (decoupled via named bars).
// Lane pair (2e, 2e+1) computes output e: half h = k in [h*64, h*64+64).
// Pair combine via shfl.bfly(1). Belief stored split [2][68] (+pad) so the
// even/odd broadcast pair hits disjoint banks. Depth-4 cp.async ring.
// ---------------------------------------------------------------------------
__global__ __launch_bounds__(512, 1) void recur_kernel(
    const float* __restrict__ Wp, const float* __restrict__ bp,
    float* __restrict__ out)
{
    __shared__ __align__(16) float bel[2][2][136];    // [buf][row][h*68 + k]
    __shared__ __align__(16) float ring[4][2][384];   // [slot][row][E|L|W]

    const int tid  = threadIdx.x;
    const int r    = tid >> 8;        // 0..1 local batch row (warps 0-7 / 8-15)
    const int t128 = tid & 255;
    const int e    = t128 >> 1;       // output lane 0..127
    const int h    = t128 & 1;        // k-half
    const long b   = (long)blockIdx.x * 2 + r;

    // Wp[e][h*64 .. h*64+64) as 32 packed f32x2 (64 regs)
    unsigned long long wp[32];
    const unsigned long long* wrow =
        (const unsigned long long*)(Wp + e * 128 + h * 64);
    #pragma unroll
    for (int i = 0; i < 32; i++) wp[i] = wrow[i];
    const float bias = bp[e];

    if (t128 < 136) bel[0][r][t128] = 0.0f;
    float belr = 0.0f;

    // prefetch: first 96 threads of each row move that row's 1536B per step
    const bool cp_on = (t128 < 96);
    const int  cp_k  = t128 * 4;
    const float* src_base = g_elw + ((long)b * TT) * 384 + cp_k;
    const uint32_t ring_base =
        (uint32_t)__cvta_generic_to_shared(&ring[0][0][0]);
    const uint32_t dst_off = (uint32_t)((r * 384 + cp_k) * 4);

    // prologue: fill slots 0..2 (t = 0..2), one commit group per slot
    for (int sl = 0; sl < 3; sl++) {
        if (cp_on) cp_async16(ring_base + (uint32_t)sl * 3072u + dst_off,
                              src_base + (long)sl * 384);
        asm volatile("cp.async.commit_group;\n");
    }

    float* outp = out + b * (long)TT * 128 + e;
    const int wh = e >> 6;                       // half that owns bel slot e
    const int widx = wh * 68 + (e & 63);

    for (int t = 0; t < TT; t++) {
        const int slot = t & 3;
        const int cur  = t & 1;

        asm volatile("cp.async.wait_group 2;\n");
        // one named barrier per row per step: ring[slot] + bel(t) visible,
        // licenses overwrite of slot (t+3)&3 and buffer cur^1
        asm volatile("bar.sync %0, %1;\n" :: "r"(r + 1), "r"(256) : "memory");

        if (t + 3 < TT && cp_on)
            cp_async16(ring_base + (uint32_t)((t + 3) & 3) * 3072u + dst_off,
                       src_base + (long)(t + 3) * 384);
        asm volatile("cp.async.commit_group;\n");

        float ev = ring[slot][r][e];
        float lv = ring[slot][r][128 + e];
        float wv = ring[slot][r][256 + e];

        const ulonglong2* bl2 =
            (const ulonglong2*)&bel[cur][r][h * 68];
        unsigned long long acc0 = 0ull, acc1 = 0ull, acc2 = 0ull, acc3 = 0ull;
        #pragma unroll
        for (int i = 0; i < 8; i++) {
            ulonglong2 b0 = bl2[2 * i];
            ulonglong2 b1 = bl2[2 * i + 1];
            acc0 = ffma2(wp[4 * i],     b0.x, acc0);
            acc1 = ffma2(wp[4 * i + 1], b0.y, acc1);
            acc2 = ffma2(wp[4 * i + 2], b1.x, acc2);
            acc3 = ffma2(wp[4 * i + 3], b1.y, acc3);
        }
        float2 s0 = u2f2(acc0);
        float2 s1 = u2f2(acc1);
        float2 s2 = u2f2(acc2);
        float2 s3 = u2f2(acc3);
        float part = ((s0.x + s0.y) + (s1.x + s1.y)) +
                     ((s2.x + s2.y) + (s3.x + s3.y));
        part += __shfl_xor_sync(0xffffffffu, part, 1);

        float pre  = part + bias + ev;
        float cand = tanh_approx(pre);
        float nb   = lv * belr + wv * cand;
        belr = nb;

        if (h == 0) outp[(long)t * 128] = nb;
        if (h == wh) bel[cur ^ 1][r][widx] = nb;  // other buffer; no 2nd bar
    }
}

// ---------------------------------------------------------------------------
// launch
// ---------------------------------------------------------------------------
extern "C" void kernel_launch(void* const* d_in, const int* in_sizes, int n_in,
                              void* d_out, int out_size) {
    const float* X  = (const float*)d_in[0];
    const float* We = (const float*)d_in[1];
    const float* be = (const float*)d_in[2];
    const float* Wp = (const float*)d_in[3];
    const float* bp = (const float*)d_in[4];
    const float* Wl = (const float*)d_in[5];
    const float* bl = (const float*)d_in[6];
    const float* Ww = (const float*)d_in[7];
    const float* bw = (const float*)d_in[8];
    float* out = (float*)d_out;

    // Xs (33.8KB) + Ws (34.8KB) = 68.6KB dynamic smem -> 2 CTAs/SM.
    cudaFuncSetAttribute(proj_kernel,
                         cudaFuncAttributeMaxDynamicSharedMemorySize, 68608);

    proj_kernel<<<MM / 64, 256, 68608>>>(X, We, be, Wl, bl, Ww, bw);
    recur_kernel<<<BB / 2, 512>>>(Wp, bp, out);
}